// round 9
// baseline (speedup 1.0000x reference)
#include <cuda_runtime.h>

// CTC forward loss — linear DP w/ per-lane block-floating-point, smem-staged
// emissions. B=128, T=1024, C=128 (blank=127), L=128, S=257.
//
// One CTA (64 threads) per batch element.
//   warp 1 (producer): reads each row, adds eps, stores the full row into a
//     64-row smem ring; also accumulates the softmax log-normalizer zsum.
//     Stays 2 phases (32 rows) ahead of the DP warp.
//   warp 0 (DP): lane l owns states 8l..8l+7 (+256 on lane 31). Emissions come
//     from the smem ring via 5 LDS/step (eps pre-added). Renorm every 4 steps;
//     the scale sck is folded into ROW t+1's emission registers (er[PH^1],
//     Round-7 timing) and sc_pm switches immediately after this step's pm1 —
//     every pm1 stays in one consistent scale frame (no delayed-frame mixing).
//   Sync: one __syncthreads per 16-step phase (uniform outer loop).
//
// loglik = log(a255+a256) + e*ln2 - zsum  (lane 31);  out = -loglik.

#define T_   1024
#define C_   128
#define L_   128
#define EPS_ 1e-7f
#define FULL 0xffffffffu
#define RING_ROWS 64
#define RING_MASK 63

// ---------------- producer: 16 rows starting at r0 ----------------
__device__ __forceinline__ void produce16(const float* __restrict__ row,
                                          float* __restrict__ ring,
                                          int g, int il, int r0, float& zs)
{
    float zp = 1.f;
#pragma unroll
    for (int rr = 0; rr < 4; ++rr) {
        const int r = r0 + rr * 4 + g;
        const float* p = row + (size_t)r * C_ + il * 16;
        float4 v0 = *(const float4*)(p);
        float4 v1 = *(const float4*)(p + 4);
        float4 v2 = *(const float4*)(p + 8);
        float4 v3 = *(const float4*)(p + 12);
        v0.x += EPS_; v0.y += EPS_; v0.z += EPS_; v0.w += EPS_;
        v1.x += EPS_; v1.y += EPS_; v1.z += EPS_; v1.w += EPS_;
        v2.x += EPS_; v2.y += EPS_; v2.z += EPS_; v2.w += EPS_;
        v3.x += EPS_; v3.y += EPS_; v3.z += EPS_; v3.w += EPS_;
        float s = ((v0.x + v0.y) + (v0.z + v0.w))
                + ((v1.x + v1.y) + (v1.z + v1.w))
                + ((v2.x + v2.y) + (v2.z + v2.w))
                + ((v3.x + v3.y) + (v3.z + v3.w));
        s += __shfl_xor_sync(FULL, s, 1);
        s += __shfl_xor_sync(FULL, s, 2);
        s += __shfl_xor_sync(FULL, s, 4);     // s = sum(p+eps) = Z + C*eps
        zp *= s;
        float* d = ring + (size_t)(r & RING_MASK) * C_ + il * 16;
        *(float4*)(d)      = v0;
        *(float4*)(d + 4)  = v1;
        *(float4*)(d + 8)  = v2;
        *(float4*)(d + 12) = v3;
    }
    zs += __logf(zp);    // 16 factors of <=128: max 2^112, no overflow
}

// One DP timestep. PH = t&1 (er slot), RS = renorm, LD = LDS row t+2.
// pm1 for step t+1 is computed BEFORE the renorm block (old sc_pm); the
// renorm folds sck into er[PH^1] (row t+1) and sets the new sc_pm, which is
// first used at end of step t+1 when registers are already in the new scale.
#define STEP(PH, t, RS, LD) {                                                  \
    const float q0 = er[PH][0], q1 = er[PH][1], q2 = er[PH][2],                \
                q3 = er[PH][3], pb = er[PH][4];                                \
    if (LD) {                                                                  \
        const float* rp = ring + (size_t)(((t) + 2) & RING_MASK) * C_;         \
        er[PH][0] = rp[cls0]; er[PH][1] = rp[cls1];                            \
        er[PH][2] = rp[cls2]; er[PH][3] = rp[cls3];                            \
        er[PH][4] = rp[C_ - 1];                                                \
    }                                                                          \
    const float n0 = (a0 + pm1) * pb;                                          \
    const float n1 = fmaf(sk0, pm1, a1 + a0) * q0;                             \
    const float n2 = (a2 + a1) * pb;                                           \
    const float n3 = fmaf(sk1, a1, a3 + a2) * q1;                              \
    const float n4 = (a4 + a3) * pb;                                           \
    const float n5 = fmaf(sk2, a3, a5 + a4) * q2;                              \
    const float n6 = (a6 + a5) * pb;                                           \
    const float n7 = fmaf(sk3, a5, a7 + a6) * q3;                              \
    const float n8 = (a256 + a7) * pb;   /* lane31: a7 == alpha[255] */        \
    a0 = n0; a1 = n1; a2 = n2; a3 = n3;                                        \
    a4 = n4; a5 = n5; a6 = n6; a7 = n7; a256 = n8;                             \
    pm1 = __shfl_up_sync(FULL, a7, 1) * sc_pm;   /* old sc_pm: for t+1 */      \
    if (RS) {                                                                  \
        float m = fmaxf(fmaxf(fmaxf(n0, n1), fmaxf(n2, n3)),                   \
                        fmaxf(fmaxf(n4, n5), fmaxf(n6, n7)));                  \
        if (lane == 31) m = fmaxf(m, n8);                                      \
        const int e_up_old = __shfl_up_sync(FULL, e, 1);                       \
        const bool has = (m > 0.f);                                            \
        const int k = has ? ((__float_as_int(m) >> 23) - 127) : 0;             \
        const float sck = __int_as_float((127 - k) << 23);                     \
        /* fold scale into row t+1's emissions (er[PH^1], read next step) */   \
        er[PH ^ 1][0] *= sck; er[PH ^ 1][1] *= sck; er[PH ^ 1][2] *= sck;      \
        er[PH ^ 1][3] *= sck; er[PH ^ 1][4] *= sck;                            \
        e = has ? (e + k) : e_up_old;    /* empty lane adopts neighbor */      \
        const int e_up2 = __shfl_up_sync(FULL, e, 1);                          \
        const int bexp = min(max(e_up2 - e + 127, 0), 254);                    \
        sc_pm = (lane == 0) ? 0.f : __int_as_float(bexp << 23);                \
    } }

// 16 steps; RS at j%4==3, PH = j&1 (tb even), LD=1.
#define BLK16(tb)                                                              \
    STEP(0, (tb)+0,  0,1) STEP(1, (tb)+1,  0,1)                                \
    STEP(0, (tb)+2,  0,1) STEP(1, (tb)+3,  1,1)                                \
    STEP(0, (tb)+4,  0,1) STEP(1, (tb)+5,  0,1)                                \
    STEP(0, (tb)+6,  0,1) STEP(1, (tb)+7,  1,1)                                \
    STEP(0, (tb)+8,  0,1) STEP(1, (tb)+9,  0,1)                                \
    STEP(0, (tb)+10, 0,1) STEP(1, (tb)+11, 1,1)                                \
    STEP(0, (tb)+12, 0,1) STEP(1, (tb)+13, 0,1)                                \
    STEP(0, (tb)+14, 0,1) STEP(1, (tb)+15, 1,1)

// Last block: no LDS past row 1023 (j=14,15), no final renorm at t=1023, so
// the outputs stay in the scale set by the t=1019 renorm (applied at t=1020).
#define BLK16_LAST(tb)                                                         \
    STEP(0, (tb)+0,  0,1) STEP(1, (tb)+1,  0,1)                                \
    STEP(0, (tb)+2,  0,1) STEP(1, (tb)+3,  1,1)                                \
    STEP(0, (tb)+4,  0,1) STEP(1, (tb)+5,  0,1)                                \
    STEP(0, (tb)+6,  0,1) STEP(1, (tb)+7,  1,1)                                \
    STEP(0, (tb)+8,  0,1) STEP(1, (tb)+9,  0,1)                                \
    STEP(0, (tb)+10, 0,1) STEP(1, (tb)+11, 1,1)                                \
    STEP(0, (tb)+12, 0,1) STEP(1, (tb)+13, 0,1)                                \
    STEP(0, (tb)+14, 0,0) STEP(1, (tb)+15, 0,0)

__global__ __launch_bounds__(64, 1)
void ctc_stage7_kernel(const int* __restrict__ y_true,
                       const float* __restrict__ y_pred,
                       float* __restrict__ out)
{
    __shared__ float ring[RING_ROWS * C_];   // 32 KB emission ring (p + eps)
    __shared__ float s_zsum;

    const int b    = blockIdx.x;
    const int tid  = threadIdx.x;
    const int lane = tid & 31;
    const int wrp  = tid >> 5;
    const float* __restrict__ row = y_pred + (size_t)b * T_ * C_;

    // ---- per-lane label config (both warps compute; warp 1 ignores) ----
    int4 c4 = *(const int4*)(y_true + b * L_ + 4 * lane);
    const int cls0 = c4.x, cls1 = c4.y, cls2 = c4.z, cls3 = c4.w;
    int clsm1 = __shfl_up_sync(FULL, cls3, 1);
    const float sk0 = (lane > 0 && cls0 != clsm1) ? 1.f : 0.f;
    const float sk1 = (cls1 != cls0) ? 1.f : 0.f;
    const float sk2 = (cls2 != cls1) ? 1.f : 0.f;
    const float sk3 = (cls3 != cls2) ? 1.f : 0.f;

    // producer-lane geometry
    const int g  = lane >> 3;
    const int il = lane & 7;
    float zs = 0.f;

    // DP state (function scope: persists across phase blocks)
    float er[2][5];
    float a0 = 0.f, a1 = 0.f, a2 = 0.f, a3 = 0.f,
          a4 = 0.f, a5 = 0.f, a6 = 0.f, a7 = 0.f, a256 = 0.f;
    int   e = 0;
    float sc_pm = (lane == 0) ? 0.f : 1.f;
    float pm1 = 0.f;
    float fin_a = 0.f, fin_c = 0.f;
    int   fin_e = 0;

    // ---- prime: producer stages rows 0..31 ----
    if (wrp == 1) {
        produce16(row, ring, g, il, 0,  zs);
        produce16(row, ring, g, il, 16, zs);
    }
    __syncthreads();

    // ---- phase 0: DP t=0..15; producer rows 32..47 ----
    if (wrp == 1) {
        produce16(row, ring, g, il, 32, zs);
    } else {
        // preload rows 0 and 1 into the register ring
        {
            const float* r0p = ring;
            er[0][0] = r0p[cls0]; er[0][1] = r0p[cls1];
            er[0][2] = r0p[cls2]; er[0][3] = r0p[cls3]; er[0][4] = r0p[C_ - 1];
            const float* r1p = ring + C_;
            er[1][0] = r1p[cls0]; er[1][1] = r1p[cls1];
            er[1][2] = r1p[cls2]; er[1][3] = r1p[cls3]; er[1][4] = r1p[C_ - 1];
        }
        // t = 0: init states 0 (blank) and 1 (first label); refill slot 0
        {
            if (lane == 0) { a0 = er[0][4]; a1 = er[0][0]; }
            const float* rp = ring + 2 * C_;
            er[0][0] = rp[cls0]; er[0][1] = rp[cls1];
            er[0][2] = rp[cls2]; er[0][3] = rp[cls3]; er[0][4] = rp[C_ - 1];
            // pm1 stays 0 (all a7 == 0 at t=0)
        }
        STEP(1, 1,  0,1) STEP(0, 2,  0,1) STEP(1, 3,  1,1)
        STEP(0, 4,  0,1) STEP(1, 5,  0,1) STEP(0, 6,  0,1) STEP(1, 7,  1,1)
        STEP(0, 8,  0,1) STEP(1, 9,  0,1) STEP(0, 10, 0,1) STEP(1, 11, 1,1)
        STEP(0, 12, 0,1) STEP(1, 13, 0,1) STEP(0, 14, 0,1) STEP(1, 15, 1,1)
    }
    __syncthreads();

    // ---- phases 1..62 ----
    for (int kk = 1; kk < 63; ++kk) {
        if (wrp == 1) {
            if (kk <= 61) produce16(row, ring, g, il, 16 * kk + 32, zs);
        } else {
            const int tb = 16 * kk;
            BLK16(tb)
        }
        __syncthreads();
    }

    // ---- phase 63: final DP block; producer folds its normalizer ----
    if (wrp == 0) {
        BLK16_LAST(1008)
        fin_a = a7;      // alpha[255] on lane 31 (scale 2^e)
        fin_c = a256;    // alpha[256] on lane 31
        fin_e = e;
    } else {
        zs += __shfl_xor_sync(FULL, zs, 8);
        zs += __shfl_xor_sync(FULL, zs, 16);
        if (lane == 0) s_zsum = zs;
    }
    __syncthreads();

    if (tid == 31) {   // warp 0, lane 31
        float ll = __logf(fin_a + fin_c) + (float)fin_e * 0.6931471805599453f
                   - s_zsum;
        out[b] = -ll;
    }
}

extern "C" void kernel_launch(void* const* d_in, const int* in_sizes, int n_in,
                              void* d_out, int out_size)
{
    const int* y_true;
    const float* y_pred;
    if (in_sizes[0] == 128 * L_) {            // y_true: [B,L] int32
        y_true = (const int*)d_in[0];
        y_pred = (const float*)d_in[1];
    } else {
        y_true = (const int*)d_in[1];
        y_pred = (const float*)d_in[0];
    }
    const int B = out_size;                    // [B,1] float32
    ctc_stage7_kernel<<<B, 64>>>(y_true, y_pred, (float*)d_out);
}